// round 2
// baseline (speedup 1.0000x reference)
#include <cuda_runtime.h>
#include <math.h>

#define Bb   2
#define Ss   2048
#define Dd   2048
#define Hh   16
#define DHd  128
#define FFf  8192
#define ROWS 4096   // B*S

// ---------------- scratch (device globals: no allocation allowed) ----------------
__device__ float g_h1[ROWS * Dd];       // ln1 output
__device__ float g_q[ROWS * Dd];
__device__ float g_k[ROWS * Dd];
__device__ float g_v[ROWS * Dd];
__device__ float g_ctx[ROWS * Dd];      // attn context (B,S,H,DH)
__device__ float g_aproj[ROWS * Dd];    // ctx @ wo
__device__ float g_h2[ROWS * Dd];       // ln2 output
__device__ float g_ffn[(size_t)ROWS * FFf]; // gelu(h2@fc_in + b)
__device__ float g_sin[Ss * 64];
__device__ float g_cos[Ss * 64];

// ---------------- RoPE tables (double-precision trig of fp32 angle) ----------------
__global__ void rope_table_kernel() {
    int t = blockIdx.x * 256 + threadIdx.x;
    if (t >= Ss * 64) return;
    int p = t >> 6, i = t & 63;
    double inv = pow(10000.0, -((double)(2 * i)) / 128.0);
    float ang = (float)p * (float)inv;   // fp32 multiply, matches numpy table build
    g_sin[t] = (float)sin((double)ang);
    g_cos[t] = (float)cos((double)ang);
}

// ---------------- LayerNorm (optionally fused residual add) ----------------
__global__ __launch_bounds__(256) void ln_kernel(
    const float* __restrict__ x, const float* __restrict__ x2,
    const float* __restrict__ g, const float* __restrict__ bta,
    float* __restrict__ out)
{
    __shared__ float red[256];
    int row = blockIdx.x, tid = threadIdx.x;
    size_t base = (size_t)row * Dd;
    float r[8];
    float s = 0.f;
#pragma unroll
    for (int t = 0; t < 8; t++) {
        int i = tid + t * 256;
        float v = x[base + i];
        if (x2) v += x2[base + i];
        r[t] = v; s += v;
    }
    red[tid] = s; __syncthreads();
    for (int o = 128; o > 0; o >>= 1) { if (tid < o) red[tid] += red[tid + o]; __syncthreads(); }
    float mean = red[0] * (1.0f / Dd);
    __syncthreads();
    float vs = 0.f;
#pragma unroll
    for (int t = 0; t < 8; t++) { float d = r[t] - mean; vs += d * d; }
    red[tid] = vs; __syncthreads();
    for (int o = 128; o > 0; o >>= 1) { if (tid < o) red[tid] += red[tid + o]; __syncthreads(); }
    float var = red[0] * (1.0f / Dd);
    float rs = rsqrtf(var + 1e-5f);
#pragma unroll
    for (int t = 0; t < 8; t++) {
        int i = tid + t * 256;
        out[base + i] = (r[t] - mean) * rs * g[i] + bta[i];
    }
}

// ---------------- RoPE application (GPT-J interleaved) ----------------
__global__ void rope_kernel(float* __restrict__ q, float* __restrict__ k,
                            const int* __restrict__ pid)
{
    int idx = blockIdx.x * 256 + threadIdx.x;   // B*S*H*64 threads exactly
    int i = idx & 63;
    int h = (idx >> 6) & 15;
    int s = (idx >> 10) & 2047;
    int b = idx >> 21;
    int pos = pid[b * Ss + s];
    float sn = g_sin[pos * 64 + i], cs = g_cos[pos * 64 + i];
    size_t o = ((size_t)(b * Ss + s)) * Dd + h * DHd + 2 * i;
    float q0 = q[o], q1 = q[o + 1];
    q[o]     = q0 * cs - q1 * sn;
    q[o + 1] = q1 * cs + q0 * sn;
    float k0 = k[o], k1 = k[o + 1];
    k[o]     = k0 * cs - k1 * sn;
    k[o + 1] = k1 * cs + k0 * sn;
}

// ---------------- generic 128x128x16 SGEMM: C = act(A@B + bias) + resid ----------------
// flags: 1=bias, 2=gelu(erf), 4=residual add
__global__ __launch_bounds__(256) void sgemm_kernel(
    const float* __restrict__ A, const float* __restrict__ Bm,
    const float* __restrict__ bias, const float* __restrict__ resid,
    float* __restrict__ C, int M, int N, int K, int flags)
{
    __shared__ float As[16][128];
    __shared__ float Bs[16][128];
    int tid = threadIdx.x;
    int m0 = blockIdx.y * 128, n0 = blockIdx.x * 128;
    int ty = tid >> 4, tx = tid & 15;
    float acc[8][8] = {};
    for (int k0 = 0; k0 < K; k0 += 16) {
#pragma unroll
        for (int l = 0; l < 2; l++) {
            int idx = tid + l * 256;
            int r = idx >> 2, c4 = (idx & 3) * 4;
            float4 av = *(const float4*)(A + (size_t)(m0 + r) * K + k0 + c4);
            As[c4][r] = av.x; As[c4 + 1][r] = av.y; As[c4 + 2][r] = av.z; As[c4 + 3][r] = av.w;
            int kk = idx >> 5, nn = (idx & 31) * 4;
            *(float4*)&Bs[kk][nn] = *(const float4*)(Bm + (size_t)(k0 + kk) * N + n0 + nn);
        }
        __syncthreads();
#pragma unroll
        for (int kk = 0; kk < 16; kk++) {
            float4 a0 = *(const float4*)&As[kk][ty * 8];
            float4 a1 = *(const float4*)&As[kk][ty * 8 + 4];
            float4 b0 = *(const float4*)&Bs[kk][tx * 8];
            float4 b1 = *(const float4*)&Bs[kk][tx * 8 + 4];
            float ra[8] = {a0.x, a0.y, a0.z, a0.w, a1.x, a1.y, a1.z, a1.w};
            float rb[8] = {b0.x, b0.y, b0.z, b0.w, b1.x, b1.y, b1.z, b1.w};
#pragma unroll
            for (int ii = 0; ii < 8; ii++)
#pragma unroll
                for (int jj = 0; jj < 8; jj++)
                    acc[ii][jj] = fmaf(ra[ii], rb[jj], acc[ii][jj]);
        }
        __syncthreads();
    }
#pragma unroll
    for (int ii = 0; ii < 8; ii++) {
        int row = m0 + ty * 8 + ii;
#pragma unroll
        for (int jj = 0; jj < 8; jj++) {
            int col = n0 + tx * 8 + jj;
            float v = acc[ii][jj];
            if (flags & 1) v += bias[col];
            if (flags & 2) v = 0.5f * v * (1.0f + erff(v * 0.70710678118654752f));
            if (flags & 4) v += resid[(size_t)row * N + col];
            C[(size_t)row * N + col] = v;
        }
    }
}

// ---------------- attention scores: logits[b,h,q,k] = Q·K, causal tile skip ----------------
__global__ __launch_bounds__(256) void score_kernel(
    const float* __restrict__ q, const float* __restrict__ k, float* __restrict__ attn)
{
    int tn = blockIdx.x, tm = blockIdx.y;
    if (tn > tm) return;  // fully masked tile; softmax pass never reads it
    int b = blockIdx.z >> 4, h = blockIdx.z & 15;
    const float* Aq = q + (size_t)b * Ss * Dd + h * DHd;
    const float* Bk = k + (size_t)b * Ss * Dd + h * DHd;
    __shared__ float Qs[16][128];
    __shared__ float Ks[16][128];
    int tid = threadIdx.x;
    int ty = tid >> 4, tx = tid & 15;
    int m0 = tm * 128, n0 = tn * 128;
    float acc[8][8] = {};
    for (int d0 = 0; d0 < DHd; d0 += 16) {
#pragma unroll
        for (int l = 0; l < 2; l++) {
            int idx = tid + l * 256;
            int r = idx >> 2, c4 = (idx & 3) * 4;
            float4 av = *(const float4*)(Aq + (size_t)(m0 + r) * Dd + d0 + c4);
            Qs[c4][r] = av.x; Qs[c4 + 1][r] = av.y; Qs[c4 + 2][r] = av.z; Qs[c4 + 3][r] = av.w;
            float4 bv = *(const float4*)(Bk + (size_t)(n0 + r) * Dd + d0 + c4);
            Ks[c4][r] = bv.x; Ks[c4 + 1][r] = bv.y; Ks[c4 + 2][r] = bv.z; Ks[c4 + 3][r] = bv.w;
        }
        __syncthreads();
#pragma unroll
        for (int kk = 0; kk < 16; kk++) {
            float4 a0 = *(const float4*)&Qs[kk][ty * 8];
            float4 a1 = *(const float4*)&Qs[kk][ty * 8 + 4];
            float4 b0 = *(const float4*)&Ks[kk][tx * 8];
            float4 b1 = *(const float4*)&Ks[kk][tx * 8 + 4];
            float ra[8] = {a0.x, a0.y, a0.z, a0.w, a1.x, a1.y, a1.z, a1.w};
            float rb[8] = {b0.x, b0.y, b0.z, b0.w, b1.x, b1.y, b1.z, b1.w};
#pragma unroll
            for (int ii = 0; ii < 8; ii++)
#pragma unroll
                for (int jj = 0; jj < 8; jj++)
                    acc[ii][jj] = fmaf(ra[ii], rb[jj], acc[ii][jj]);
        }
        __syncthreads();
    }
    float* Cb = attn + ((size_t)(b * Hh + h) * Ss) * Ss;
#pragma unroll
    for (int ii = 0; ii < 8; ii++)
#pragma unroll
        for (int jj = 0; jj < 8; jj++)
            Cb[(size_t)(m0 + ty * 8 + ii) * Ss + n0 + tx * 8 + jj] = acc[ii][jj];
}

// ---------------- row softmax with causal truncation (writes exact zeros above diag) ----------------
__global__ __launch_bounds__(256) void softmax_kernel(float* __restrict__ attn)
{
    int rid = blockIdx.x;               // b*H*S + h*S + q
    int qpos = rid & (Ss - 1);
    int L = qpos + 1;
    float* row = attn + (size_t)rid * Ss;
    __shared__ float red[256];
    int tid = threadIdx.x;
    float r[8];
    float mx = -3.4e38f;
#pragma unroll
    for (int t = 0; t < 8; t++) {
        int i = tid + t * 256;
        float v = (i < L) ? row[i] : -3.4e38f;
        r[t] = v; mx = fmaxf(mx, v);
    }
    red[tid] = mx; __syncthreads();
    for (int o = 128; o > 0; o >>= 1) { if (tid < o) red[tid] = fmaxf(red[tid], red[tid + o]); __syncthreads(); }
    mx = red[0]; __syncthreads();
    float s = 0.f;
#pragma unroll
    for (int t = 0; t < 8; t++) {
        int i = tid + t * 256;
        float e = (i < L) ? expf(r[t] - mx) : 0.0f;
        r[t] = e; s += e;
    }
    red[tid] = s; __syncthreads();
    for (int o = 128; o > 0; o >>= 1) { if (tid < o) red[tid] += red[tid + o]; __syncthreads(); }
    float inv = 1.0f / red[0];
#pragma unroll
    for (int t = 0; t < 8; t++)
        row[tid + t * 256] = r[t] * inv;
}

// ---------------- ctx = attn_weights @ V (causally truncated K loop) ----------------
__global__ __launch_bounds__(256) void ctx_kernel(
    const float* __restrict__ attn, const float* __restrict__ v, float* __restrict__ ctx)
{
    int tm = blockIdx.y;
    int b = blockIdx.z >> 4, h = blockIdx.z & 15;
    const float* W = attn + ((size_t)(b * Hh + h) * Ss) * Ss;
    const float* V = v + (size_t)b * Ss * Dd + h * DHd;
    __shared__ float As[16][128];
    __shared__ float Bs[16][128];
    int tid = threadIdx.x;
    int ty = tid >> 4, tx = tid & 15;
    int m0 = tm * 128;
    float acc[8][8] = {};
    int Kend = (tm + 1) * 128;   // weights are exactly zero beyond the diagonal
    for (int k0 = 0; k0 < Kend; k0 += 16) {
#pragma unroll
        for (int l = 0; l < 2; l++) {
            int idx = tid + l * 256;
            int r = idx >> 2, c4 = (idx & 3) * 4;
            float4 av = *(const float4*)(W + (size_t)(m0 + r) * Ss + k0 + c4);
            As[c4][r] = av.x; As[c4 + 1][r] = av.y; As[c4 + 2][r] = av.z; As[c4 + 3][r] = av.w;
            int kk = idx >> 5, nn = (idx & 31) * 4;
            *(float4*)&Bs[kk][nn] = *(const float4*)(V + (size_t)(k0 + kk) * Dd + nn);
        }
        __syncthreads();
#pragma unroll
        for (int kk = 0; kk < 16; kk++) {
            float4 a0 = *(const float4*)&As[kk][ty * 8];
            float4 a1 = *(const float4*)&As[kk][ty * 8 + 4];
            float4 b0 = *(const float4*)&Bs[kk][tx * 8];
            float4 b1 = *(const float4*)&Bs[kk][tx * 8 + 4];
            float ra[8] = {a0.x, a0.y, a0.z, a0.w, a1.x, a1.y, a1.z, a1.w};
            float rb[8] = {b0.x, b0.y, b0.z, b0.w, b1.x, b1.y, b1.z, b1.w};
#pragma unroll
            for (int ii = 0; ii < 8; ii++)
#pragma unroll
                for (int jj = 0; jj < 8; jj++)
                    acc[ii][jj] = fmaf(ra[ii], rb[jj], acc[ii][jj]);
        }
        __syncthreads();
    }
#pragma unroll
    for (int ii = 0; ii < 8; ii++)
#pragma unroll
        for (int jj = 0; jj < 8; jj++)
            ctx[(size_t)(b * Ss + m0 + ty * 8 + ii) * Dd + h * DHd + tx * 8 + jj] = acc[ii][jj];
}

// ---------------- launch ----------------
extern "C" void kernel_launch(void* const* d_in, const int* in_sizes, int n_in,
                              void* d_out, int out_size)
{
    const float* hs   = (const float*)d_in[0];
    const int*   pid  = (const int*)  d_in[1];
    const float* wq   = (const float*)d_in[2];
    const float* wk   = (const float*)d_in[3];
    const float* wv   = (const float*)d_in[4];
    const float* wo   = (const float*)d_in[5];
    const float* ln1g = (const float*)d_in[6];
    const float* ln1b = (const float*)d_in[7];
    const float* ln2g = (const float*)d_in[8];
    const float* ln2b = (const float*)d_in[9];
    const float* fiw  = (const float*)d_in[10];
    const float* fib  = (const float*)d_in[11];
    const float* fow  = (const float*)d_in[12];
    const float* fob  = (const float*)d_in[13];

    float* out  = (float*)d_out;
    float* attn = out + (size_t)ROWS * Dd;   // attn_weights region, also logits scratch

    float *h1, *q, *k, *v, *ctx, *aproj, *h2, *ffn;
    cudaGetSymbolAddress((void**)&h1,    g_h1);
    cudaGetSymbolAddress((void**)&q,     g_q);
    cudaGetSymbolAddress((void**)&k,     g_k);
    cudaGetSymbolAddress((void**)&v,     g_v);
    cudaGetSymbolAddress((void**)&ctx,   g_ctx);
    cudaGetSymbolAddress((void**)&aproj, g_aproj);
    cudaGetSymbolAddress((void**)&h2,    g_h2);
    cudaGetSymbolAddress((void**)&ffn,   g_ffn);

    rope_table_kernel<<<512, 256>>>();

    // ln1
    ln_kernel<<<ROWS, 256>>>(hs, nullptr, ln1g, ln1b, h1);

    // QKV projections
    sgemm_kernel<<<dim3(16, 32), 256>>>(h1, wq, nullptr, nullptr, q, ROWS, Dd, Dd, 0);
    sgemm_kernel<<<dim3(16, 32), 256>>>(h1, wk, nullptr, nullptr, k, ROWS, Dd, Dd, 0);
    sgemm_kernel<<<dim3(16, 32), 256>>>(h1, wv, nullptr, nullptr, v, ROWS, Dd, Dd, 0);

    // RoPE on q,k
    rope_kernel<<<(Bb * Ss * Hh * 64) / 256, 256>>>(q, k, pid);

    // scores -> softmax -> ctx
    score_kernel<<<dim3(16, 16, Bb * Hh), 256>>>(q, k, attn);
    softmax_kernel<<<Bb * Hh * Ss, 256>>>(attn);
    ctx_kernel<<<dim3(1, 16, Bb * Hh), 256>>>(attn, v, ctx);

    // output projection
    sgemm_kernel<<<dim3(16, 32), 256>>>(ctx, wo, nullptr, nullptr, aproj, ROWS, Dd, Dd, 0);

    // ln2 over (hidden + attn_proj)
    ln_kernel<<<ROWS, 256>>>(hs, aproj, ln2g, ln2b, h2);

    // FFN
    sgemm_kernel<<<dim3(64, 32), 256>>>(h2, fiw, fib, nullptr, ffn, ROWS, FFf, Dd, 1 | 2);
    sgemm_kernel<<<dim3(16, 32), 256>>>(ffn, fow, fob, h2, out, ROWS, Dd, FFf, 1 | 4);
}

// round 4
// speedup vs baseline: 2.6454x; 2.6454x over previous
#include <cuda_runtime.h>
#include <cuda_bf16.h>
#include <math.h>
#include <stdint.h>

#define Bb   2
#define Ss   2048
#define Dd   2048
#define Hh   16
#define DHd  128
#define FFf  8192
#define ROWS 4096   // B*S

// ================= scratch (device globals) =================
__device__ float g_h1[(size_t)ROWS * Dd];
__device__ float g_qkv[(size_t)3 * ROWS * Dd];
__device__ float g_ctx[(size_t)ROWS * Dd];
__device__ float g_aproj[(size_t)ROWS * Dd];
__device__ float g_h2[(size_t)ROWS * Dd];
__device__ float g_ffn[(size_t)ROWS * FFf];
__device__ float g_wqkvt[(size_t)3 * Dd * Dd];     // K-major [6144][2048]
__device__ float g_wot[(size_t)Dd * Dd];
__device__ float g_fiwt[(size_t)Dd * FFf];         // [8192][2048]
__device__ float g_fowt[(size_t)Dd * FFf];         // [2048][8192]
__device__ float g_vt[(size_t)Bb * Hh * DHd * Ss]; // [bh][dh][S]
__device__ float g_sin[Ss * 64];
__device__ float g_cos[Ss * 64];

// ================= mma.sync helpers =================
__device__ __forceinline__ uint32_t smem_u32(const void* p) {
    uint32_t a;
    asm("{ .reg .u64 t; cvta.to.shared.u64 t, %1; cvt.u32.u64 %0, t; }" : "=r"(a) : "l"(p));
    return a;
}
__device__ __forceinline__ void ldm4(uint32_t* r, uint32_t addr) {
    asm volatile("ldmatrix.sync.aligned.m8n8.x4.shared.b16 {%0,%1,%2,%3}, [%4];"
        : "=r"(r[0]), "=r"(r[1]), "=r"(r[2]), "=r"(r[3]) : "r"(addr));
}
__device__ __forceinline__ void ldm2(uint32_t* r, uint32_t addr) {
    asm volatile("ldmatrix.sync.aligned.m8n8.x2.shared.b16 {%0,%1}, [%2];"
        : "=r"(r[0]), "=r"(r[1]) : "r"(addr));
}
__device__ __forceinline__ void mma_bf16(float* c, const uint32_t* a, const uint32_t* b) {
    asm volatile(
        "mma.sync.aligned.m16n8k16.row.col.f32.bf16.bf16.f32 "
        "{%0,%1,%2,%3}, {%4,%5,%6,%7}, {%8,%9}, {%0,%1,%2,%3};"
        : "+f"(c[0]), "+f"(c[1]), "+f"(c[2]), "+f"(c[3])
        : "r"(a[0]), "r"(a[1]), "r"(a[2]), "r"(a[3]), "r"(b[0]), "r"(b[1]));
}
__device__ __forceinline__ void split_pack(float x, float y, uint32_t& hi, uint32_t& lo) {
    float hx = __bfloat162float(__float2bfloat16_rn(x));
    float hy = __bfloat162float(__float2bfloat16_rn(y));
    __nv_bfloat162 h2 = __floats2bfloat162_rn(hx, hy);
    __nv_bfloat162 l2 = __floats2bfloat162_rn(x - hx, y - hy);
    hi = *reinterpret_cast<uint32_t*>(&h2);
    lo = *reinterpret_cast<uint32_t*>(&l2);
}

// ================= RoPE tables =================
__global__ void rope_table_kernel() {
    int t = blockIdx.x * 256 + threadIdx.x;
    if (t >= Ss * 64) return;
    int p = t >> 6, i = t & 63;
    double inv = pow(10000.0, -((double)(2 * i)) / 128.0);
    float ang = (float)p * (float)inv;
    g_sin[t] = (float)sin((double)ang);
    g_cos[t] = (float)cos((double)ang);
}

// ================= weight transpose =================
__global__ __launch_bounds__(256) void transpose_kernel(
    const float* __restrict__ in, float* __restrict__ out, int R, int Cc)
{
    __shared__ float t[32][33];
    int bx = blockIdx.x * 32, by = blockIdx.y * 32;
    int tx = threadIdx.x, ty = threadIdx.y;
#pragma unroll
    for (int i = 0; i < 32; i += 8)
        t[ty + i][tx] = in[(size_t)(by + ty + i) * Cc + bx + tx];
    __syncthreads();
#pragma unroll
    for (int i = 0; i < 32; i += 8)
        out[(size_t)(bx + ty + i) * R + by + tx] = t[tx][ty + i];
}

// V^T per head: vt[bh][n][s] = v[b][s][h*128+n]
__global__ __launch_bounds__(256) void vtrans_kernel(
    const float* __restrict__ v, float* __restrict__ vt)
{
    __shared__ float t[32][33];
    int bh = blockIdx.z;
    int b = bh >> 4, h = bh & 15;
    const float* in = v + (size_t)b * Ss * Dd + h * DHd;
    float* out = vt + (size_t)bh * DHd * Ss;
    int s0 = blockIdx.x * 32, n0 = blockIdx.y * 32;
    int tx = threadIdx.x, ty = threadIdx.y;
#pragma unroll
    for (int i = 0; i < 32; i += 8)
        t[ty + i][tx] = in[(size_t)(s0 + ty + i) * Dd + n0 + tx];
    __syncthreads();
#pragma unroll
    for (int i = 0; i < 32; i += 8)
        out[(size_t)(n0 + ty + i) * Ss + s0 + tx] = t[tx][ty + i];
}

// ================= LayerNorm =================
__global__ __launch_bounds__(256) void ln_kernel(
    const float* __restrict__ x, const float* __restrict__ x2,
    const float* __restrict__ g, const float* __restrict__ bta,
    float* __restrict__ out)
{
    __shared__ float red[256];
    int row = blockIdx.x, tid = threadIdx.x;
    size_t base = (size_t)row * Dd;
    float r[8];
    float s = 0.f;
#pragma unroll
    for (int t = 0; t < 8; t++) {
        int i = tid + t * 256;
        float v = x[base + i];
        if (x2) v += x2[base + i];
        r[t] = v; s += v;
    }
    red[tid] = s; __syncthreads();
    for (int o = 128; o > 0; o >>= 1) { if (tid < o) red[tid] += red[tid + o]; __syncthreads(); }
    float mean = red[0] * (1.0f / Dd);
    __syncthreads();
    float vs = 0.f;
#pragma unroll
    for (int t = 0; t < 8; t++) { float d = r[t] - mean; vs += d * d; }
    red[tid] = vs; __syncthreads();
    for (int o = 128; o > 0; o >>= 1) { if (tid < o) red[tid] += red[tid + o]; __syncthreads(); }
    float var = red[0] * (1.0f / Dd);
    float rs = rsqrtf(var + 1e-5f);
#pragma unroll
    for (int t = 0; t < 8; t++) {
        int i = tid + t * 256;
        out[base + i] = (r[t] - mean) * rs * g[i] + bta[i];
    }
}

// ================= RoPE =================
__global__ void rope_kernel(float* __restrict__ q, float* __restrict__ k,
                            const int* __restrict__ pid)
{
    int idx = blockIdx.x * 256 + threadIdx.x;
    int i = idx & 63;
    int h = (idx >> 6) & 15;
    int s = (idx >> 10) & 2047;
    int b = idx >> 21;
    int pos = pid[b * Ss + s];
    float sn = g_sin[pos * 64 + i], cs = g_cos[pos * 64 + i];
    size_t o = ((size_t)(b * Ss + s)) * Dd + h * DHd + 2 * i;
    float q0 = q[o], q1 = q[o + 1];
    q[o]     = q0 * cs - q1 * sn;
    q[o + 1] = q1 * cs + q0 * sn;
    float k0 = k[o], k1 = k[o + 1];
    k[o]     = k0 * cs - k1 * sn;
    k[o + 1] = k1 * cs + k0 * sn;
}

// ================= bf16x3 mma.sync GEMM =================
// C = act(A[M,K] @ Bt[N,K]^T + bias) + resid
// flags: 1=bias 2=gelu 4=resid 8=qkv-scatter 16=score(causal skip) 32=ctx(K trunc)
// smem per buffer: Ahi(10240) Alo(10240) Bhi(10240) Blo(10240) = 40960; x2 buffers
#define SMB 40960u
#define SMT (2u * SMB)

__global__ __launch_bounds__(256) void gemm_mma(
    const float* __restrict__ A, const float* __restrict__ Bt,
    const float* __restrict__ bias, const float* __restrict__ resid,
    float* __restrict__ C, int K,
    int lda, int ldb, int ldc, int flags)
{
    extern __shared__ char sm[];
    int bx = blockIdx.x, by = blockIdx.y, bz = blockIdx.z;
    const float* Ap = A;
    const float* Bp = Bt;
    float* Cp = C;
    int Keff = K;
    if (flags & 16) {                 // scores: Q.K^T per (b,h), causal tile skip
        if (bx > by) return;
        int b = bz >> 4, h = bz & 15;
        Ap += (size_t)b * Ss * Dd + h * DHd;
        Bp += (size_t)b * Ss * Dd + h * DHd;
        Cp += (size_t)bz * Ss * Ss;
    }
    if (flags & 32) {                 // ctx: attn @ V, truncated K
        int b = bz >> 4, h = bz & 15;
        Ap += (size_t)bz * Ss * Ss;
        Bp += (size_t)bz * DHd * Ss;
        Cp += (size_t)b * Ss * Dd + h * DHd;
        Keff = (by + 1) * 128;
    }
    const int tid = threadIdx.x, lane = tid & 31, warp = tid >> 5;
    const int m0 = by * 128, n0 = bx * 128;
    const int wm = (warp >> 2) * 64, wn = (warp & 3) * 32;
    const uint32_t sbase = smem_u32(sm);

    float acc[4][4][4];
#pragma unroll
    for (int i = 0; i < 4; i++)
#pragma unroll
        for (int j = 0; j < 4; j++)
#pragma unroll
            for (int e = 0; e < 4; e++) acc[i][j][e] = 0.f;

    const int r_ld = tid >> 3;              // 0..31? no: tid/8 -> 0..31
    const int c4_ld = (tid & 7) * 4;        // 0..28
    float4 ra[4], rb[4];

#define LOAD_CHUNK(K0) { \
    _Pragma("unroll") \
    for (int i = 0; i < 4; i++) { \
        int r = r_ld + i * 32; \
        ra[i] = *(const float4*)(Ap + (size_t)(m0 + r) * lda + (K0) + c4_ld); \
        rb[i] = *(const float4*)(Bp + (size_t)(n0 + r) * ldb + (K0) + c4_ld); \
    } }

#define STS_CHUNK(BOFF) { \
    _Pragma("unroll") \
    for (int i = 0; i < 4; i++) { \
        int r = r_ld + i * 32; \
        uint32_t off = (BOFF) + (uint32_t)r * 80u + (uint32_t)c4_ld * 2u; \
        uint2 ha, la, hb, lb; \
        split_pack(ra[i].x, ra[i].y, ha.x, la.x); \
        split_pack(ra[i].z, ra[i].w, ha.y, la.y); \
        split_pack(rb[i].x, rb[i].y, hb.x, lb.x); \
        split_pack(rb[i].z, rb[i].w, hb.y, lb.y); \
        *(uint2*)(sm + off)              = ha; \
        *(uint2*)(sm + off + 10240u)     = la; \
        *(uint2*)(sm + off + 20480u)     = hb; \
        *(uint2*)(sm + off + 30720u)     = lb; \
    } }

    const int nch = Keff / 32;
    LOAD_CHUNK(0);
    STS_CHUNK(0u);
    __syncthreads();

    const uint32_t a_lane_off = (uint32_t)(wm + (lane & 15)) * 80u + (uint32_t)((lane >> 4) * 16);
    const uint32_t b_lane_off = (uint32_t)(wn + (lane & 7)) * 80u + (uint32_t)(((lane >> 3) & 1) * 16);

    for (int c = 0; c < nch; c++) {
        const uint32_t boff = (uint32_t)(c & 1) * SMB;
        if (c + 1 < nch) LOAD_CHUNK((c + 1) * 32);
#pragma unroll
        for (int ks = 0; ks < 2; ks++) {
            uint32_t ahi[4][4], alo[4][4], bhi[4][2], blo[4][2];
            uint32_t abase = sbase + boff + a_lane_off + (uint32_t)(ks * 32);
            uint32_t bbase = sbase + boff + 20480u + b_lane_off + (uint32_t)(ks * 32);
#pragma unroll
            for (int mti = 0; mti < 4; mti++) {
                ldm4(ahi[mti], abase + (uint32_t)(mti * 16) * 80u);
                ldm4(alo[mti], abase + (uint32_t)(mti * 16) * 80u + 10240u);
            }
#pragma unroll
            for (int ntj = 0; ntj < 4; ntj++) {
                ldm2(bhi[ntj], bbase + (uint32_t)(ntj * 8) * 80u);
                ldm2(blo[ntj], bbase + (uint32_t)(ntj * 8) * 80u + 10240u);
            }
#pragma unroll
            for (int mti = 0; mti < 4; mti++)
#pragma unroll
                for (int ntj = 0; ntj < 4; ntj++) {
                    mma_bf16(acc[mti][ntj], ahi[mti], bhi[ntj]);
                    mma_bf16(acc[mti][ntj], ahi[mti], blo[ntj]);
                    mma_bf16(acc[mti][ntj], alo[mti], bhi[ntj]);
                }
        }
        if (c + 1 < nch) STS_CHUNK((uint32_t)((c + 1) & 1) * SMB);
        __syncthreads();
    }

    // ---------------- epilogue ----------------
#pragma unroll
    for (int mti = 0; mti < 4; mti++) {
#pragma unroll
        for (int ntj = 0; ntj < 4; ntj++) {
            int row = m0 + wm + mti * 16 + (lane >> 2);
            int col = n0 + wn + ntj * 8 + (lane & 3) * 2;
#pragma unroll
            for (int half = 0; half < 2; half++) {
                int rr = row + half * 8;
                float v0 = acc[mti][ntj][half * 2];
                float v1 = acc[mti][ntj][half * 2 + 1];
                if (flags & 1) { v0 += bias[col]; v1 += bias[col + 1]; }
                if (flags & 2) {
                    v0 = 0.5f * v0 * (1.0f + erff(v0 * 0.70710678118654752f));
                    v1 = 0.5f * v1 * (1.0f + erff(v1 * 0.70710678118654752f));
                }
                if (flags & 4) {
                    const float* rp = resid + (size_t)rr * ldc + col;
                    v0 += rp[0]; v1 += rp[1];
                }
                float2 o = make_float2(v0, v1);
                if (flags & 8) {
                    int sel = col >> 11, cl = col & 2047;
                    *(float2*)(Cp + (size_t)sel * ROWS * Dd + (size_t)rr * Dd + cl) = o;
                } else {
                    *(float2*)(Cp + (size_t)rr * ldc + col) = o;
                }
            }
        }
    }
}

// ================= row softmax (causal truncation) =================
__global__ __launch_bounds__(256) void softmax_kernel(float* __restrict__ attn)
{
    int rid = blockIdx.x;
    int qpos = rid & (Ss - 1);
    int L = qpos + 1;
    float* row = attn + (size_t)rid * Ss;
    __shared__ float red[256];
    int tid = threadIdx.x;
    float r[8];
    float mx = -3.4e38f;
#pragma unroll
    for (int t = 0; t < 8; t++) {
        int i = tid + t * 256;
        float v = (i < L) ? row[i] : -3.4e38f;
        r[t] = v; mx = fmaxf(mx, v);
    }
    red[tid] = mx; __syncthreads();
    for (int o = 128; o > 0; o >>= 1) { if (tid < o) red[tid] = fmaxf(red[tid], red[tid + o]); __syncthreads(); }
    mx = red[0]; __syncthreads();
    float s = 0.f;
#pragma unroll
    for (int t = 0; t < 8; t++) {
        int i = tid + t * 256;
        float e = (i < L) ? expf(r[t] - mx) : 0.0f;
        r[t] = e; s += e;
    }
    red[tid] = s; __syncthreads();
    for (int o = 128; o > 0; o >>= 1) { if (tid < o) red[tid] += red[tid + o]; __syncthreads(); }
    float inv = 1.0f / red[0];
#pragma unroll
    for (int t = 0; t < 8; t++)
        row[tid + t * 256] = r[t] * inv;
}

// ================= launch =================
extern "C" void kernel_launch(void* const* d_in, const int* in_sizes, int n_in,
                              void* d_out, int out_size)
{
    const float* hs   = (const float*)d_in[0];
    const int*   pid  = (const int*)  d_in[1];
    const float* wq   = (const float*)d_in[2];
    const float* wk   = (const float*)d_in[3];
    const float* wv   = (const float*)d_in[4];
    const float* wo   = (const float*)d_in[5];
    const float* ln1g = (const float*)d_in[6];
    const float* ln1b = (const float*)d_in[7];
    const float* ln2g = (const float*)d_in[8];
    const float* ln2b = (const float*)d_in[9];
    const float* fiw  = (const float*)d_in[10];
    const float* fib  = (const float*)d_in[11];
    const float* fow  = (const float*)d_in[12];
    const float* fob  = (const float*)d_in[13];

    float* out  = (float*)d_out;
    float* attn = out + (size_t)ROWS * Dd;

    float *h1, *qkv, *ctx, *aproj, *h2, *ffn, *wqkvt, *wot, *fiwt, *fowt, *vt;
    cudaGetSymbolAddress((void**)&h1,    g_h1);
    cudaGetSymbolAddress((void**)&qkv,   g_qkv);
    cudaGetSymbolAddress((void**)&ctx,   g_ctx);
    cudaGetSymbolAddress((void**)&aproj, g_aproj);
    cudaGetSymbolAddress((void**)&h2,    g_h2);
    cudaGetSymbolAddress((void**)&ffn,   g_ffn);
    cudaGetSymbolAddress((void**)&wqkvt, g_wqkvt);
    cudaGetSymbolAddress((void**)&wot,   g_wot);
    cudaGetSymbolAddress((void**)&fiwt,  g_fiwt);
    cudaGetSymbolAddress((void**)&fowt,  g_fowt);
    cudaGetSymbolAddress((void**)&vt,    g_vt);

    float* q = qkv;
    float* k = qkv + (size_t)ROWS * Dd;
    float* v = qkv + (size_t)2 * ROWS * Dd;

    cudaFuncSetAttribute(gemm_mma, cudaFuncAttributeMaxDynamicSharedMemorySize, SMT);

    rope_table_kernel<<<512, 256>>>();

    dim3 tb(32, 8);
    transpose_kernel<<<dim3(Dd / 32, Dd / 32), tb>>>(wq, wqkvt, Dd, Dd);
    transpose_kernel<<<dim3(Dd / 32, Dd / 32), tb>>>(wk, wqkvt + (size_t)Dd * Dd, Dd, Dd);
    transpose_kernel<<<dim3(Dd / 32, Dd / 32), tb>>>(wv, wqkvt + (size_t)2 * Dd * Dd, Dd, Dd);
    transpose_kernel<<<dim3(Dd / 32, Dd / 32), tb>>>(wo, wot, Dd, Dd);
    transpose_kernel<<<dim3(FFf / 32, Dd / 32), tb>>>(fiw, fiwt, Dd, FFf);
    transpose_kernel<<<dim3(Dd / 32, FFf / 32), tb>>>(fow, fowt, FFf, Dd);

    ln_kernel<<<ROWS, 256>>>(hs, nullptr, ln1g, ln1b, h1);

    // fused QKV projection
    gemm_mma<<<dim3(48, 32), 256, SMT>>>(h1, wqkvt, nullptr, nullptr, qkv,
                                         Dd, Dd, Dd, Dd, 8);

    rope_kernel<<<(Bb * Ss * Hh * 64) / 256, 256>>>(q, k, pid);
    vtrans_kernel<<<dim3(Ss / 32, DHd / 32, Bb * Hh), tb>>>(v, vt);

    // scores (causal) -> softmax -> ctx
    gemm_mma<<<dim3(16, 16, Bb * Hh), 256, SMT>>>(q, k, nullptr, nullptr, attn,
                                                  DHd, Dd, Dd, Ss, 16);
    softmax_kernel<<<Bb * Hh * Ss, 256>>>(attn);
    gemm_mma<<<dim3(1, 16, Bb * Hh), 256, SMT>>>(attn, vt, nullptr, nullptr, ctx,
                                                 Ss, Ss, Ss, Dd, 32);

    // output projection
    gemm_mma<<<dim3(16, 32), 256, SMT>>>(ctx, wot, nullptr, nullptr, aproj,
                                         Dd, Dd, Dd, Dd, 0);

    ln_kernel<<<ROWS, 256>>>(hs, aproj, ln2g, ln2b, h2);

    // FFN
    gemm_mma<<<dim3(64, 32), 256, SMT>>>(h2, fiwt, fib, nullptr, ffn,
                                         Dd, Dd, Dd, FFf, 1 | 2);
    gemm_mma<<<dim3(16, 32), 256, SMT>>>(ffn, fowt, fob, h2, out,
                                         FFf, FFf, FFf, Dd, 1 | 4);
}